// round 15
// baseline (speedup 1.0000x reference)
#include <cuda_runtime.h>
#include <cuda_fp16.h>
#include <cstdint>
#include <math.h>

#define B_  128
#define T_  480
#define C1  64
#define C2  128
#define C3  128

#define S1_ (B_*T_*C1)
#define S2_ (B_*T_*C2)
#define S3_ (B_*T_*C3)

// Padded fp16 spike buffers (rows padded for dilated taps).
#define P1F 64
#define R1_ (P1F + T_ + 160)      // 704 rows  (conv2 max row 637)
#define P2F 192
#define R2_ (P2F + T_ + 608)      // 1280 rows (conv3 max row 889)

#define SPK1_ELEMS ((long)B_*R1_*C1)
#define SPK2_ELEMS ((long)B_*R2_*C2)

#define LO_SCALE 2048.0f
#define LO_INV   (1.0f/2048.0f)

#define NTILES   1024            // (4 mtiles) x (2 otiles) x (128 batches)
#define PERSIST  296             // 148 SM x 2 CTAs/SM

// ---------------- device scratch (allocation-free) ----------------
// __device__ globals are .bss zero-initialized; g_spkh pads are never
// written by any kernel, so they stay zero across replays (no memset).
__device__ float g_x1[S1_];
__device__ float g_x2[S2_];
__device__ float g_x3[S3_];
__device__ __align__(256) __half g_spkh[SPK1_ELEMS + SPK2_ELEMS];
__device__ __align__(256) __half g_wt2[2*128*2048];   // [limb][o][kk]
__device__ __align__(256) __half g_wt3[2*128*4096];
__device__ int g_cnt[2];                              // work-steal counters

// ---------------- PTX helpers (sm_80-era features only) ----------------
__device__ __forceinline__ uint32_t smem_to_u32(const void* p) {
    uint32_t a;
    asm("{ .reg .u64 t; cvta.to.shared.u64 t, %1; cvt.u32.u64 %0, t; }" : "=r"(a) : "l"(p));
    return a;
}
#define SWZ(x) ((x) ^ (((x) >> 3) & 0x70))

#define CP_ASYNC16(sa, gp) \
    asm volatile("cp.async.cg.shared.global [%0], [%1], 16;" \
        :: "r"(sa), "l"(__cvta_generic_to_global(gp)) : "memory")
#define CP_COMMIT() asm volatile("cp.async.commit_group;" ::: "memory")
#define CP_WAIT1()  asm volatile("cp.async.wait_group 1;" ::: "memory")
#define CP_WAIT0()  asm volatile("cp.async.wait_group 0;" ::: "memory")

#define LDSM_X4(r, addr) \
    asm volatile("ldmatrix.sync.aligned.m8n8.x4.shared.b16 {%0,%1,%2,%3}, [%4];" \
        : "=r"((r)[0]), "=r"((r)[1]), "=r"((r)[2]), "=r"((r)[3]) : "r"(addr))

#define MMA16816(c, a, b0, b1) \
    asm volatile("mma.sync.aligned.m16n8k16.row.col.f32.f16.f16.f32 " \
        "{%0,%1,%2,%3}, {%4,%5,%6,%7}, {%8,%9}, {%0,%1,%2,%3};" \
        : "+f"((c)[0]), "+f"((c)[1]), "+f"((c)[2]), "+f"((c)[3]) \
        : "r"((a)[0]), "r"((a)[1]), "r"((a)[2]), "r"((a)[3]), "r"(b0), "r"(b1))

// ---------------------------------------------------------------------------
// Counter reset (graph position 0; makes every replay identical)
// ---------------------------------------------------------------------------
__global__ void reset_kernel() {
    g_cnt[0] = 0;
    g_cnt[1] = 0;
}

// ---------------------------------------------------------------------------
// conv1 + BN1: register-tiled 64x64 GEMM per 64-row tile (R14 winner).
// ---------------------------------------------------------------------------
__global__ __launch_bounds__(256)
void conv1_bn_kernel(const float* __restrict__ x, const float* __restrict__ w1,
                     const float* __restrict__ sc, const float* __restrict__ bi,
                     const float* __restrict__ mn, const float* __restrict__ vr,
                     float* __restrict__ out) {
    const int LDP = 68;
    __shared__ float As[64*LDP];
    __shared__ float Bs[64*LDP];
    int tid = threadIdx.x;
    int tx = tid & 15, ty = tid >> 4;
    long row0 = (long)blockIdx.x*64;

    #pragma unroll
    for (int rep = 0; rep < 16; rep++) {
        int e = rep*256 + tid;
        int tl = e >> 6, w = e & 63;
        As[w*LDP + tl] = x[(row0 + tl)*64 + w];
        Bs[(e >> 6)*LDP + (e & 63)] = w1[e];
    }
    __syncthreads();

    float acc[4][4];
    #pragma unroll
    for (int r = 0; r < 4; r++)
        #pragma unroll
        for (int c = 0; c < 4; c++) acc[r][c] = 0.f;

    #pragma unroll 16
    for (int w = 0; w < 64; w++) {
        float4 a4 = *(const float4*)&As[w*LDP + ty*4];
        float4 b4 = *(const float4*)&Bs[w*LDP + tx*4];
        float ar[4] = {a4.x, a4.y, a4.z, a4.w};
        float br[4] = {b4.x, b4.y, b4.z, b4.w};
        #pragma unroll
        for (int r = 0; r < 4; r++)
            #pragma unroll
            for (int c = 0; c < 4; c++)
                acc[r][c] = fmaf(ar[r], br[c], acc[r][c]);
    }

    float gs[4], hb[4];
    #pragma unroll
    for (int c = 0; c < 4; c++) {
        int o = tx*4 + c;
        float inv = rsqrtf(vr[o] + 1e-5f);
        gs[c] = sc[o]*inv;
        hb[c] = bi[o] - mn[o]*gs[c];
    }
    #pragma unroll
    for (int r = 0; r < 4; r++) {
        long rw = (row0 + ty*4 + r)*64;
        float4 o4;
        o4.x = fmaf(acc[r][0], gs[0], hb[0]);
        o4.y = fmaf(acc[r][1], gs[1], hb[1]);
        o4.z = fmaf(acc[r][2], gs[2], hb[2]);
        o4.w = fmaf(acc[r][3], gs[3], hb[3]);
        *(float4*)&out[rw + tx*4] = o4;
    }
}

// ---------------------------------------------------------------------------
// Weight prep: transpose + 2-limb fp16 split (lo scaled by 2048).
// ---------------------------------------------------------------------------
__global__ void wprep_both_kernel(const float* __restrict__ w, __half* __restrict__ wt,
                                  int KTOT) {
    int idx = blockIdx.x*256 + threadIdx.x;
    if (idx >= 128*KTOT) return;
    int o = idx / KTOT, kk = idx % KTOT;
    float v = w[(long)kk*128 + o];
    __half hi = __float2half(v);
    wt[idx] = hi;
    wt[(long)128*KTOT + idx] = __float2half((v - __half2float(hi)) * LO_SCALE);
}

// ---------------------------------------------------------------------------
// HLIF scan, DEPTH-deep software prefetch.
// ---------------------------------------------------------------------------
template<int C, int Rp, int PFp, int DEPTH>
__global__ __launch_bounds__(128)
void hlif_kernel(const float* __restrict__ xin, float* __restrict__ spk,
                 __half* __restrict__ spkh,
                 const float* __restrict__ vth_raw,
                 const float* __restrict__ decay_raw,
                 float v_m, float v_s, float d_m, float d_s) {
    int idx = blockIdx.x*128 + threadIdx.x;
    int b = idx / C, c = idx % C;
    float vth = log1pf(expf(vth_raw[c]*v_s + v_m)) + 0.5f;
    float decay = fminf(1.f/(1.f + expf(-(decay_raw[c]*d_s + d_m))), 0.99f);
    long base = (long)b*T_*C + c;
    long bb   = ((long)b*Rp + PFp)*C + c;
    float v = 0.f;
    float xv[DEPTH], xn[DEPTH];
    #pragma unroll
    for (int j = 0; j < DEPTH; j++) xv[j] = xin[base + (long)j*C];
    for (int t = 0; t < T_; t += DEPTH) {
        if (t + DEPTH < T_) {
            #pragma unroll
            for (int j = 0; j < DEPTH; j++) xn[j] = xin[base + (long)(t+DEPTH+j)*C];
        }
        #pragma unroll
        for (int j = 0; j < DEPTH; j++) {
            v = v*decay + xv[j];
            float s = (v - vth) > 0.f ? 1.f : 0.f;
            v -= s*vth;
            spk[base + (long)(t+j)*C] = s;
            spkh[bb + (long)(t+j)*C] = __float2half(s);
        }
        #pragma unroll
        for (int j = 0; j < DEPTH; j++) xv[j] = xn[j];
    }
}

// ---------------------------------------------------------------------------
// ALIF scan, 32-deep software prefetch.
// ---------------------------------------------------------------------------
__global__ __launch_bounds__(128)
void alif_kernel(const float* __restrict__ xin, float* __restrict__ spk) {
    const float d = 0.9f, adp = 0.9f, beta = 1.8f;
    int idx = blockIdx.x*128 + threadIdx.x;
    int b = idx / C3, c = idx % C3;
    long base = (long)b*T_*C3 + c;
    float v = 0.f, th = 0.f, ps = 0.f;
    float xv[32], xn[32];
    #pragma unroll
    for (int j = 0; j < 32; j++) xv[j] = xin[base + (long)j*C3];
    for (int t = 0; t < T_; t += 32) {
        if (t + 32 < T_) {
            #pragma unroll
            for (int j = 0; j < 32; j++) xn[j] = xin[base + (long)(t+32+j)*C3];
        }
        #pragma unroll
        for (int j = 0; j < 32; j++) {
            th = th*adp + ps*beta;
            v  = v*d + xv[j];
            float vt = 0.5f + th;
            float s = (v - vt) > 0.f ? 1.f : 0.f;
            v -= s*vt;
            ps = s;
            spk[base + (long)(t+j)*C3] = s;
        }
        #pragma unroll
        for (int j = 0; j < 32; j++) xv[j] = xn[j];
    }
}

// ---------------------------------------------------------------------------
// Persistent HMMA dilated conv + BN. 296 CTAs work-steal 1024 tiles via
// atomic counter (tile-exclusive writes -> deterministic output).
// CTA tile 128(t) x 64(cout), 2 CTAs/SM, 3-stage cp.async per tile.
// ---------------------------------------------------------------------------
#define STAGE_BYTES 32768
#define CSMEM_BYTES (3*STAGE_BYTES)

template<int CID, int CIN, int DIL, int PADL, int PF, int Rp, int NITER>
__global__ __launch_bounds__(256, 2)
void conv_mma_kernel(const __half* __restrict__ src, const __half* __restrict__ wt,
                     const float* __restrict__ sc, const float* __restrict__ bi,
                     const float* __restrict__ mn, const float* __restrict__ vr,
                     float* __restrict__ dst) {
    constexpr int KTOT = NITER*64;
    constexpr int CHUNKS = CIN/64;
    extern __shared__ char smem[];
    __shared__ float gsm[128], hbm[128];     // both otiles' BN params
    __shared__ int s_idx;
    const int tid = threadIdx.x, lane = tid & 31, wid = tid >> 5;
    const int warpM = wid & 3, warpN = wid >> 2;   // 4(M) x 2(N)

    if (tid < 128) {
        float inv = rsqrtf(vr[tid] + 1e-5f);
        float g = sc[tid]*inv;
        gsm[tid] = g;
        hbm[tid] = bi[tid] - mn[tid]*g;
    }

    const uint32_t sbase = smem_to_u32(smem);

    while (true) {
        if (tid == 0) s_idx = atomicAdd(&g_cnt[CID], 1);
        __syncthreads();
        const int tile = s_idx;
        if (tile >= NTILES) break;
        const int b     = tile >> 3;
        const int mtile = (tile >> 1) & 3;
        const int oBase = (tile & 1)*64;
        const __half* sb = src + (long)b*Rp*CIN;

        float accH[2][4][4] = {};
        float accL[2][4][4] = {};

        auto issue = [&](int it) {
            const uint32_t stage = sbase + (uint32_t)(it % 3)*(uint32_t)STAGE_BYTES;
            const int k  = it / CHUNKS;
            const int c0 = (it % CHUNKS)*64;
            const long arow0 = (long)(PF + mtile*128 + k*DIL - PADL);
            #pragma unroll
            for (int rep = 0; rep < 4; rep++) {
                int idx = rep*256 + tid;
                int row = idx >> 3, seg = idx & 7;
                const __half* gp = sb + (arow0 + row)*CIN + c0 + seg*8;
                CP_ASYNC16(stage + SWZ(row*128 + seg*16), gp);
            }
            #pragma unroll
            for (int limb = 0; limb < 2; limb++) {
                const __half* wp = wt + (long)limb*128*KTOT + (long)oBase*KTOT + it*64;
                #pragma unroll
                for (int rep = 0; rep < 2; rep++) {
                    int idx = rep*256 + tid;
                    int row = idx >> 3, seg = idx & 7;
                    const __half* gp = wp + (long)row*KTOT + seg*8;
                    CP_ASYNC16(stage + 16384u + (uint32_t)limb*8192u + SWZ(row*128 + seg*16), gp);
                }
            }
            CP_COMMIT();
        };

        issue(0);
        issue(1);
        __syncthreads();

        for (int it = 0; it < NITER; it++) {
            if (it + 2 < NITER) CP_WAIT1(); else CP_WAIT0();
            __syncthreads();
            if (it + 2 < NITER) issue(it + 2);

            const uint32_t stage = sbase + (uint32_t)(it % 3)*(uint32_t)STAGE_BYTES;

            #pragma unroll
            for (int ks = 0; ks < 4; ks++) {
                uint32_t a[2][4];
                #pragma unroll
                for (int mf = 0; mf < 2; mf++) {
                    int row = warpM*32 + mf*16 + (lane & 15);
                    LDSM_X4(a[mf], stage + SWZ(row*128 + ks*32 + (lane >> 4)*16));
                }
                #pragma unroll
                for (int limb = 0; limb < 2; limb++) {
                    const uint32_t bbp = stage + 16384u + (uint32_t)limb*8192u;
                    #pragma unroll
                    for (int np = 0; np < 2; np++) {
                        int row = warpN*32 + np*16 + ((lane >> 4) << 3) + (lane & 7);
                        uint32_t q[4];
                        LDSM_X4(q, bbp + SWZ(row*128 + ks*32 + ((lane >> 3) & 1)*16));
                        if (limb == 0) {
                            #pragma unroll
                            for (int mf = 0; mf < 2; mf++) {
                                MMA16816(accH[mf][np*2],     a[mf], q[0], q[1]);
                                MMA16816(accH[mf][np*2 + 1], a[mf], q[2], q[3]);
                            }
                        } else {
                            #pragma unroll
                            for (int mf = 0; mf < 2; mf++) {
                                MMA16816(accL[mf][np*2],     a[mf], q[0], q[1]);
                                MMA16816(accL[mf][np*2 + 1], a[mf], q[2], q[3]);
                            }
                        }
                    }
                }
            }
        }

        #pragma unroll
        for (int mf = 0; mf < 2; mf++) {
            #pragma unroll
            for (int h = 0; h < 2; h++) {
                int t = mtile*128 + warpM*32 + mf*16 + (lane >> 2) + h*8;
                if (t < T_) {
                    long dr = ((long)b*T_ + t)*128 + oBase;
                    #pragma unroll
                    for (int ng = 0; ng < 4; ng++) {
                        int lc = warpN*32 + ng*8 + (lane & 3)*2;
                        float v0 = fmaf(accL[mf][ng][h*2],     LO_INV, accH[mf][ng][h*2]);
                        float v1 = fmaf(accL[mf][ng][h*2 + 1], LO_INV, accH[mf][ng][h*2 + 1]);
                        float2 o;
                        o.x = fmaf(v0, gsm[oBase + lc],   hbm[oBase + lc]);
                        o.y = fmaf(v1, gsm[oBase + lc+1], hbm[oBase + lc+1]);
                        *(float2*)&dst[dr + lc] = o;
                    }
                }
            }
        }
        __syncthreads();   // protect s_idx for next iteration
    }
}

// ---------------------------------------------------------------------------
// Readout: dense -> LI scan -> window diff -> attention -> logits
// ---------------------------------------------------------------------------
__global__ __launch_bounds__(256)
void readout_kernel(const float* __restrict__ spk3,
                    const float* __restrict__ dw, const float* __restrict__ db,
                    const float* __restrict__ a1w, const float* __restrict__ a1b,
                    const float* __restrict__ a2w, const float* __restrict__ a2b,
                    float* __restrict__ logits) {
    __shared__ float vseq[T_*4];
    __shared__ float dp[20*4];
    __shared__ float hsm[20*8];
    __shared__ float score[20];
    __shared__ float wsm[128*4];
    int b = blockIdx.x, tid = threadIdx.x;
    for (int e = tid; e < 512; e += 256) wsm[e] = dw[e];
    __syncthreads();
    const float* sp = spk3 + (long)b*T_*C3;
    for (int e = tid; e < T_*4; e += 256) {
        int t = e >> 2, j = e & 3;
        float accv = db[j];
        const float* row = sp + (long)t*C3;
        #pragma unroll 8
        for (int c = 0; c < 128; c++) accv = fmaf(row[c], wsm[c*4 + j], accv);
        vseq[e] = accv;
    }
    __syncthreads();
    if (tid < 4) {
        float v = 0.f;
        const float dec = 0.9f, odec = 0.1f;
        for (int t = 0; t < T_; t++) {
            v = fmaf(v, dec, vseq[t*4 + tid]*odec);
            vseq[t*4 + tid] = v;
        }
    }
    __syncthreads();
    if (tid < 80) {
        int g = tid >> 2, j = tid & 3;
        float s1 = 0.f, s2 = 0.f;
        #pragma unroll
        for (int u = 0; u < 12; u++) {
            s1 += vseq[(g*24 + u)*4 + j];
            s2 += vseq[(g*24 + 12 + u)*4 + j];
        }
        dp[g*4 + j] = (s2 - s1)*(1.f/12.f);
    }
    __syncthreads();
    if (tid < 160) {
        int g = tid >> 3, u = tid & 7;
        float a = a1b[u];
        #pragma unroll
        for (int j = 0; j < 4; j++) a = fmaf(dp[g*4 + j], a1w[j*8 + u], a);
        hsm[g*8 + u] = fmaxf(a, 0.f);
    }
    __syncthreads();
    if (tid < 20) {
        float a = a2b[0];
        #pragma unroll
        for (int u = 0; u < 8; u++) a = fmaf(hsm[tid*8 + u], a2w[u], a);
        score[tid] = a;
    }
    __syncthreads();
    if (tid < 4) {
        float m = -1e30f;
        #pragma unroll
        for (int g = 0; g < 20; g++) m = fmaxf(m, score[g]);
        float den = 0.f, accv = 0.f;
        #pragma unroll
        for (int g = 0; g < 20; g++) {
            float e = expf(score[g] - m);
            den += e;
            accv = fmaf(dp[g*4 + tid], e, accv);
        }
        logits[b*4 + tid] = accv/den;
    }
}

// ---------------------------------------------------------------------------
extern "C" void kernel_launch(void* const* d_in, const int* in_sizes, int n_in,
                              void* d_out, int out_size) {
    const float* x    = (const float*)d_in[0];
    const float* w1   = (const float*)d_in[1];
    const float* bn1s = (const float*)d_in[2];
    const float* bn1b = (const float*)d_in[3];
    const float* bn1m = (const float*)d_in[4];
    const float* bn1v = (const float*)d_in[5];
    const float* vth1 = (const float*)d_in[6];
    const float* dec1 = (const float*)d_in[7];
    const float* w2   = (const float*)d_in[8];
    const float* bn2s = (const float*)d_in[9];
    const float* bn2b = (const float*)d_in[10];
    const float* bn2m = (const float*)d_in[11];
    const float* bn2v = (const float*)d_in[12];
    const float* vth2 = (const float*)d_in[13];
    const float* dec2 = (const float*)d_in[14];
    const float* w3   = (const float*)d_in[15];
    const float* bn3s = (const float*)d_in[16];
    const float* bn3b = (const float*)d_in[17];
    const float* bn3m = (const float*)d_in[18];
    const float* bn3v = (const float*)d_in[19];
    const float* dw   = (const float*)d_in[20];
    const float* db   = (const float*)d_in[21];
    const float* a1w  = (const float*)d_in[22];
    const float* a1b  = (const float*)d_in[23];
    const float* a2w  = (const float*)d_in[24];
    const float* a2b  = (const float*)d_in[25];

    float* out  = (float*)d_out;
    float* spk1 = out + 512;
    float* spk2 = spk1 + S1_;
    float* spk3 = spk2 + S2_;

    void *px1, *px2, *px3, *psp, *pw2, *pw3;
    cudaGetSymbolAddress(&px1, g_x1);
    cudaGetSymbolAddress(&px2, g_x2);
    cudaGetSymbolAddress(&px3, g_x3);
    cudaGetSymbolAddress(&psp, g_spkh);
    cudaGetSymbolAddress(&pw2, g_wt2);
    cudaGetSymbolAddress(&pw3, g_wt3);
    float* x1p = (float*)px1;
    float* x2p = (float*)px2;
    float* x3p = (float*)px3;
    __half* s1h = (__half*)psp;
    __half* s2h = s1h + SPK1_ELEMS;
    __half* wt2 = (__half*)pw2;
    __half* wt3 = (__half*)pw3;

    cudaFuncSetAttribute(conv_mma_kernel<0, C1, 4, 62, P1F, R1_, 32>,
                         cudaFuncAttributeMaxDynamicSharedMemorySize, CSMEM_BYTES);
    cudaFuncSetAttribute(conv_mma_kernel<1, C2, 12, 186, P2F, R2_, 64>,
                         cudaFuncAttributeMaxDynamicSharedMemorySize, CSMEM_BYTES);

    // Launch order (ncu -s 5 -c 1 => index 5 = conv2):
    // 0: reset, 1: wprep2, 2: wprep3, 3: conv1, 4: hlif1, 5: conv2
    reset_kernel<<<1, 1>>>();
    wprep_both_kernel<<<(128*2048 + 255)/256, 256>>>(w2, wt2, 2048);
    wprep_both_kernel<<<(128*4096 + 255)/256, 256>>>(w3, wt3, 4096);

    conv1_bn_kernel<<<B_*T_/64, 256>>>(x, w1, bn1s, bn1b, bn1m, bn1v, x1p);
    hlif_kernel<C1, R1_, P1F, 16><<<B_*C1/128, 128>>>(x1p, spk1, s1h, vth1, dec1,
                                                      0.f, 1.f, 2.f, 1.f);
    conv_mma_kernel<0, C1, 4, 62, P1F, R1_, 32><<<PERSIST, 256, CSMEM_BYTES>>>(
        s1h, wt2, bn2s, bn2b, bn2m, bn2v, x2p);
    hlif_kernel<C2, R2_, P2F, 32><<<B_*C2/128, 128>>>(x2p, spk2, s2h, vth2, dec2,
                                                      0.f, 1.f, 2.f, 1.f);
    conv_mma_kernel<1, C2, 12, 186, P2F, R2_, 64><<<PERSIST, 256, CSMEM_BYTES>>>(
        s2h, wt3, bn3s, bn3b, bn3m, bn3v, x3p);
    alif_kernel<<<B_*C3/128, 128>>>(x3p, spk3);
    readout_kernel<<<B_, 256>>>(spk3, dw, db, a1w, a1b, a2w, a2b, out);
}

// round 16
// speedup vs baseline: 1.2884x; 1.2884x over previous
#include <cuda_runtime.h>
#include <cuda_fp16.h>
#include <cstdint>
#include <math.h>

#define B_  128
#define T_  480
#define C1  64
#define C2  128
#define C3  128

#define S1_ (B_*T_*C1)
#define S2_ (B_*T_*C2)
#define S3_ (B_*T_*C3)

// Padded fp16 spike buffers (rows padded for dilated taps).
#define P1F 64
#define R1_ (P1F + T_ + 160)      // 704 rows  (conv2 max row 637)
#define P2F 192
#define R2_ (P2F + T_ + 608)      // 1280 rows (conv3 max row 889)

#define SPK1_ELEMS ((long)B_*R1_*C1)
#define SPK2_ELEMS ((long)B_*R2_*C2)

#define LO_SCALE 2048.0f
#define LO_INV   (1.0f/2048.0f)

#define NTILES   1024
#define PERSIST  296             // 148 SM x 2 CTAs/SM

// ---------------- device scratch (allocation-free) ----------------
// __device__ globals are .bss zero-initialized; g_spkh pads are never
// written by any kernel, so they stay zero across replays (no memset).
__device__ float g_x1[S1_];
__device__ float g_x2[S2_];
__device__ float g_x3[S3_];
__device__ __align__(256) __half g_spkh[SPK1_ELEMS + SPK2_ELEMS];
__device__ __align__(256) __half g_wt2[2*128*2048];   // [limb][o][kk]
__device__ __align__(256) __half g_wt3[2*128*4096];

// ---------------- PTX helpers (sm_80-era features only) ----------------
__device__ __forceinline__ uint32_t smem_to_u32(const void* p) {
    uint32_t a;
    asm("{ .reg .u64 t; cvta.to.shared.u64 t, %1; cvt.u32.u64 %0, t; }" : "=r"(a) : "l"(p));
    return a;
}
#define SWZ(x) ((x) ^ (((x) >> 3) & 0x70))

#define CP_ASYNC16(sa, gp) \
    asm volatile("cp.async.cg.shared.global [%0], [%1], 16;" \
        :: "r"(sa), "l"(__cvta_generic_to_global(gp)) : "memory")
#define CP_COMMIT() asm volatile("cp.async.commit_group;" ::: "memory")
#define CP_WAIT1()  asm volatile("cp.async.wait_group 1;" ::: "memory")
#define CP_WAIT0()  asm volatile("cp.async.wait_group 0;" ::: "memory")

#define LDSM_X4(r, addr) \
    asm volatile("ldmatrix.sync.aligned.m8n8.x4.shared.b16 {%0,%1,%2,%3}, [%4];" \
        : "=r"((r)[0]), "=r"((r)[1]), "=r"((r)[2]), "=r"((r)[3]) : "r"(addr))

#define MMA16816(c, a, b0, b1) \
    asm volatile("mma.sync.aligned.m16n8k16.row.col.f32.f16.f16.f32 " \
        "{%0,%1,%2,%3}, {%4,%5,%6,%7}, {%8,%9}, {%0,%1,%2,%3};" \
        : "+f"((c)[0]), "+f"((c)[1]), "+f"((c)[2]), "+f"((c)[3]) \
        : "r"((a)[0]), "r"((a)[1]), "r"((a)[2]), "r"((a)[3]), "r"(b0), "r"(b1))

// ---------------------------------------------------------------------------
// conv1 + BN1: register-tiled 64x64 GEMM per 64-row tile (R14 winner).
// ---------------------------------------------------------------------------
__global__ __launch_bounds__(256)
void conv1_bn_kernel(const float* __restrict__ x, const float* __restrict__ w1,
                     const float* __restrict__ sc, const float* __restrict__ bi,
                     const float* __restrict__ mn, const float* __restrict__ vr,
                     float* __restrict__ out) {
    const int LDP = 68;
    __shared__ float As[64*LDP];
    __shared__ float Bs[64*LDP];
    int tid = threadIdx.x;
    int tx = tid & 15, ty = tid >> 4;
    long row0 = (long)blockIdx.x*64;

    #pragma unroll
    for (int rep = 0; rep < 16; rep++) {
        int e = rep*256 + tid;
        int tl = e >> 6, w = e & 63;
        As[w*LDP + tl] = x[(row0 + tl)*64 + w];
        Bs[(e >> 6)*LDP + (e & 63)] = w1[e];
    }
    __syncthreads();

    float acc[4][4];
    #pragma unroll
    for (int r = 0; r < 4; r++)
        #pragma unroll
        for (int c = 0; c < 4; c++) acc[r][c] = 0.f;

    #pragma unroll 16
    for (int w = 0; w < 64; w++) {
        float4 a4 = *(const float4*)&As[w*LDP + ty*4];
        float4 b4 = *(const float4*)&Bs[w*LDP + tx*4];
        float ar[4] = {a4.x, a4.y, a4.z, a4.w};
        float br[4] = {b4.x, b4.y, b4.z, b4.w};
        #pragma unroll
        for (int r = 0; r < 4; r++)
            #pragma unroll
            for (int c = 0; c < 4; c++)
                acc[r][c] = fmaf(ar[r], br[c], acc[r][c]);
    }

    float gs[4], hb[4];
    #pragma unroll
    for (int c = 0; c < 4; c++) {
        int o = tx*4 + c;
        float inv = rsqrtf(vr[o] + 1e-5f);
        gs[c] = sc[o]*inv;
        hb[c] = bi[o] - mn[o]*gs[c];
    }
    #pragma unroll
    for (int r = 0; r < 4; r++) {
        long rw = (row0 + ty*4 + r)*64;
        float4 o4;
        o4.x = fmaf(acc[r][0], gs[0], hb[0]);
        o4.y = fmaf(acc[r][1], gs[1], hb[1]);
        o4.z = fmaf(acc[r][2], gs[2], hb[2]);
        o4.w = fmaf(acc[r][3], gs[3], hb[3]);
        *(float4*)&out[rw + tx*4] = o4;
    }
}

// ---------------------------------------------------------------------------
// Weight prep: transpose + fp16 limb (limb 0 = hi; limb 1 = lo scaled 2048).
// ---------------------------------------------------------------------------
template<int LIMB>
__global__ void wprep_kernel(const float* __restrict__ w, __half* __restrict__ wt,
                             int KTOT) {
    int idx = blockIdx.x*256 + threadIdx.x;
    if (idx >= 128*KTOT) return;
    int o = idx / KTOT, kk = idx % KTOT;
    float v = w[(long)kk*128 + o];
    if (LIMB == 0) {
        wt[idx] = __float2half(v);
    } else {
        __half hi = __float2half(v);
        wt[(long)128*KTOT + idx] = __float2half((v - __half2float(hi)) * LO_SCALE);
    }
}
__global__ void wprep_both_kernel(const float* __restrict__ w, __half* __restrict__ wt,
                                  int KTOT) {
    int idx = blockIdx.x*256 + threadIdx.x;
    if (idx >= 128*KTOT) return;
    int o = idx / KTOT, kk = idx % KTOT;
    float v = w[(long)kk*128 + o];
    __half hi = __float2half(v);
    wt[idx] = hi;
    wt[(long)128*KTOT + idx] = __float2half((v - __half2float(hi)) * LO_SCALE);
}

// ---------------------------------------------------------------------------
// HLIF scan, DEPTH-deep software prefetch.
// ---------------------------------------------------------------------------
template<int C, int Rp, int PFp, int DEPTH>
__global__ __launch_bounds__(128)
void hlif_kernel(const float* __restrict__ xin, float* __restrict__ spk,
                 __half* __restrict__ spkh,
                 const float* __restrict__ vth_raw,
                 const float* __restrict__ decay_raw,
                 float v_m, float v_s, float d_m, float d_s) {
    int idx = blockIdx.x*128 + threadIdx.x;
    int b = idx / C, c = idx % C;
    float vth = log1pf(expf(vth_raw[c]*v_s + v_m)) + 0.5f;
    float decay = fminf(1.f/(1.f + expf(-(decay_raw[c]*d_s + d_m))), 0.99f);
    long base = (long)b*T_*C + c;
    long bb   = ((long)b*Rp + PFp)*C + c;
    float v = 0.f;
    float xv[DEPTH], xn[DEPTH];
    #pragma unroll
    for (int j = 0; j < DEPTH; j++) xv[j] = xin[base + (long)j*C];
    for (int t = 0; t < T_; t += DEPTH) {
        if (t + DEPTH < T_) {
            #pragma unroll
            for (int j = 0; j < DEPTH; j++) xn[j] = xin[base + (long)(t+DEPTH+j)*C];
        }
        #pragma unroll
        for (int j = 0; j < DEPTH; j++) {
            v = v*decay + xv[j];
            float s = (v - vth) > 0.f ? 1.f : 0.f;
            v -= s*vth;
            spk[base + (long)(t+j)*C] = s;
            spkh[bb + (long)(t+j)*C] = __float2half(s);
        }
        #pragma unroll
        for (int j = 0; j < DEPTH; j++) xv[j] = xn[j];
    }
}

// ---------------------------------------------------------------------------
// ALIF scan, 32-deep software prefetch.
// ---------------------------------------------------------------------------
__global__ __launch_bounds__(128)
void alif_kernel(const float* __restrict__ xin, float* __restrict__ spk) {
    const float d = 0.9f, adp = 0.9f, beta = 1.8f;
    int idx = blockIdx.x*128 + threadIdx.x;
    int b = idx / C3, c = idx % C3;
    long base = (long)b*T_*C3 + c;
    float v = 0.f, th = 0.f, ps = 0.f;
    float xv[32], xn[32];
    #pragma unroll
    for (int j = 0; j < 32; j++) xv[j] = xin[base + (long)j*C3];
    for (int t = 0; t < T_; t += 32) {
        if (t + 32 < T_) {
            #pragma unroll
            for (int j = 0; j < 32; j++) xn[j] = xin[base + (long)(t+32+j)*C3];
        }
        #pragma unroll
        for (int j = 0; j < 32; j++) {
            th = th*adp + ps*beta;
            v  = v*d + xv[j];
            float vt = 0.5f + th;
            float s = (v - vt) > 0.f ? 1.f : 0.f;
            v -= s*vt;
            ps = s;
            spk[base + (long)(t+j)*C3] = s;
        }
        #pragma unroll
        for (int j = 0; j < 32; j++) xv[j] = xn[j];
    }
}

// ---------------------------------------------------------------------------
// Persistent HMMA dilated conv + BN — STATIC strided assignment (no atomics).
// 296 CTAs; CTA k handles tiles k, k+296, ... Tile decode matches R14's
// (otile fastest) to preserve A-tile L2 pairing. Body identical to R14.
// ---------------------------------------------------------------------------
#define STAGE_BYTES 32768
#define CSMEM_BYTES (3*STAGE_BYTES)

template<int CIN, int DIL, int PADL, int PF, int Rp, int NITER>
__global__ __launch_bounds__(256, 2)
void conv_mma_kernel(const __half* __restrict__ src, const __half* __restrict__ wt,
                     const float* __restrict__ sc, const float* __restrict__ bi,
                     const float* __restrict__ mn, const float* __restrict__ vr,
                     float* __restrict__ dst) {
    constexpr int KTOT = NITER*64;
    constexpr int CHUNKS = CIN/64;
    extern __shared__ char smem[];
    __shared__ float gsm[128], hbm[128];
    const int tid = threadIdx.x, lane = tid & 31, wid = tid >> 5;
    const int warpM = wid & 3, warpN = wid >> 2;   // 4(M) x 2(N)

    if (tid < 128) {
        float inv = rsqrtf(vr[tid] + 1e-5f);
        float g = sc[tid]*inv;
        gsm[tid] = g;
        hbm[tid] = bi[tid] - mn[tid]*g;
    }
    __syncthreads();

    const uint32_t sbase = smem_to_u32(smem);

    for (int tile = blockIdx.x; tile < NTILES; tile += PERSIST) {
        const int b     = tile >> 3;
        const int mtile = (tile >> 1) & 3;
        const int oBase = (tile & 1)*64;
        const __half* sb = src + (long)b*Rp*CIN;

        float accH[2][4][4] = {};
        float accL[2][4][4] = {};

        auto issue = [&](int it) {
            const uint32_t stage = sbase + (uint32_t)(it % 3)*(uint32_t)STAGE_BYTES;
            const int k  = it / CHUNKS;
            const int c0 = (it % CHUNKS)*64;
            const long arow0 = (long)(PF + mtile*128 + k*DIL - PADL);
            #pragma unroll
            for (int rep = 0; rep < 4; rep++) {
                int idx = rep*256 + tid;
                int row = idx >> 3, seg = idx & 7;
                const __half* gp = sb + (arow0 + row)*CIN + c0 + seg*8;
                CP_ASYNC16(stage + SWZ(row*128 + seg*16), gp);
            }
            #pragma unroll
            for (int limb = 0; limb < 2; limb++) {
                const __half* wp = wt + (long)limb*128*KTOT + (long)oBase*KTOT + it*64;
                #pragma unroll
                for (int rep = 0; rep < 2; rep++) {
                    int idx = rep*256 + tid;
                    int row = idx >> 3, seg = idx & 7;
                    const __half* gp = wp + (long)row*KTOT + seg*8;
                    CP_ASYNC16(stage + 16384u + (uint32_t)limb*8192u + SWZ(row*128 + seg*16), gp);
                }
            }
            CP_COMMIT();
        };

        issue(0);
        issue(1);
        __syncthreads();

        for (int it = 0; it < NITER; it++) {
            if (it + 2 < NITER) CP_WAIT1(); else CP_WAIT0();
            __syncthreads();
            if (it + 2 < NITER) issue(it + 2);

            const uint32_t stage = sbase + (uint32_t)(it % 3)*(uint32_t)STAGE_BYTES;

            #pragma unroll
            for (int ks = 0; ks < 4; ks++) {
                uint32_t a[2][4];
                #pragma unroll
                for (int mf = 0; mf < 2; mf++) {
                    int row = warpM*32 + mf*16 + (lane & 15);
                    LDSM_X4(a[mf], stage + SWZ(row*128 + ks*32 + (lane >> 4)*16));
                }
                #pragma unroll
                for (int limb = 0; limb < 2; limb++) {
                    const uint32_t bbp = stage + 16384u + (uint32_t)limb*8192u;
                    #pragma unroll
                    for (int np = 0; np < 2; np++) {
                        int row = warpN*32 + np*16 + ((lane >> 4) << 3) + (lane & 7);
                        uint32_t q[4];
                        LDSM_X4(q, bbp + SWZ(row*128 + ks*32 + ((lane >> 3) & 1)*16));
                        if (limb == 0) {
                            #pragma unroll
                            for (int mf = 0; mf < 2; mf++) {
                                MMA16816(accH[mf][np*2],     a[mf], q[0], q[1]);
                                MMA16816(accH[mf][np*2 + 1], a[mf], q[2], q[3]);
                            }
                        } else {
                            #pragma unroll
                            for (int mf = 0; mf < 2; mf++) {
                                MMA16816(accL[mf][np*2],     a[mf], q[0], q[1]);
                                MMA16816(accL[mf][np*2 + 1], a[mf], q[2], q[3]);
                            }
                        }
                    }
                }
            }
        }

        #pragma unroll
        for (int mf = 0; mf < 2; mf++) {
            #pragma unroll
            for (int h = 0; h < 2; h++) {
                int t = mtile*128 + warpM*32 + mf*16 + (lane >> 2) + h*8;
                if (t < T_) {
                    long dr = ((long)b*T_ + t)*128 + oBase;
                    #pragma unroll
                    for (int ng = 0; ng < 4; ng++) {
                        int lc = warpN*32 + ng*8 + (lane & 3)*2;
                        float v0 = fmaf(accL[mf][ng][h*2],     LO_INV, accH[mf][ng][h*2]);
                        float v1 = fmaf(accL[mf][ng][h*2 + 1], LO_INV, accH[mf][ng][h*2 + 1]);
                        float2 o;
                        o.x = fmaf(v0, gsm[oBase + lc],   hbm[oBase + lc]);
                        o.y = fmaf(v1, gsm[oBase + lc+1], hbm[oBase + lc+1]);
                        *(float2*)&dst[dr + lc] = o;
                    }
                }
            }
        }
        __syncthreads();
    }
}

// ---------------------------------------------------------------------------
// Readout: dense -> LI scan -> window diff -> attention -> logits
// ---------------------------------------------------------------------------
__global__ __launch_bounds__(256)
void readout_kernel(const float* __restrict__ spk3,
                    const float* __restrict__ dw, const float* __restrict__ db,
                    const float* __restrict__ a1w, const float* __restrict__ a1b,
                    const float* __restrict__ a2w, const float* __restrict__ a2b,
                    float* __restrict__ logits) {
    __shared__ float vseq[T_*4];
    __shared__ float dp[20*4];
    __shared__ float hsm[20*8];
    __shared__ float score[20];
    __shared__ float wsm[128*4];
    int b = blockIdx.x, tid = threadIdx.x;
    for (int e = tid; e < 512; e += 256) wsm[e] = dw[e];
    __syncthreads();
    const float* sp = spk3 + (long)b*T_*C3;
    for (int e = tid; e < T_*4; e += 256) {
        int t = e >> 2, j = e & 3;
        float accv = db[j];
        const float* row = sp + (long)t*C3;
        #pragma unroll 8
        for (int c = 0; c < 128; c++) accv = fmaf(row[c], wsm[c*4 + j], accv);
        vseq[e] = accv;
    }
    __syncthreads();
    if (tid < 4) {
        float v = 0.f;
        const float dec = 0.9f, odec = 0.1f;
        for (int t = 0; t < T_; t++) {
            v = fmaf(v, dec, vseq[t*4 + tid]*odec);
            vseq[t*4 + tid] = v;
        }
    }
    __syncthreads();
    if (tid < 80) {
        int g = tid >> 2, j = tid & 3;
        float s1 = 0.f, s2 = 0.f;
        #pragma unroll
        for (int u = 0; u < 12; u++) {
            s1 += vseq[(g*24 + u)*4 + j];
            s2 += vseq[(g*24 + 12 + u)*4 + j];
        }
        dp[g*4 + j] = (s2 - s1)*(1.f/12.f);
    }
    __syncthreads();
    if (tid < 160) {
        int g = tid >> 3, u = tid & 7;
        float a = a1b[u];
        #pragma unroll
        for (int j = 0; j < 4; j++) a = fmaf(dp[g*4 + j], a1w[j*8 + u], a);
        hsm[g*8 + u] = fmaxf(a, 0.f);
    }
    __syncthreads();
    if (tid < 20) {
        float a = a2b[0];
        #pragma unroll
        for (int u = 0; u < 8; u++) a = fmaf(hsm[tid*8 + u], a2w[u], a);
        score[tid] = a;
    }
    __syncthreads();
    if (tid < 4) {
        float m = -1e30f;
        #pragma unroll
        for (int g = 0; g < 20; g++) m = fmaxf(m, score[g]);
        float den = 0.f, accv = 0.f;
        #pragma unroll
        for (int g = 0; g < 20; g++) {
            float e = expf(score[g] - m);
            den += e;
            accv = fmaf(dp[g*4 + tid], e, accv);
        }
        logits[b*4 + tid] = accv/den;
    }
}

// ---------------------------------------------------------------------------
extern "C" void kernel_launch(void* const* d_in, const int* in_sizes, int n_in,
                              void* d_out, int out_size) {
    const float* x    = (const float*)d_in[0];
    const float* w1   = (const float*)d_in[1];
    const float* bn1s = (const float*)d_in[2];
    const float* bn1b = (const float*)d_in[3];
    const float* bn1m = (const float*)d_in[4];
    const float* bn1v = (const float*)d_in[5];
    const float* vth1 = (const float*)d_in[6];
    const float* dec1 = (const float*)d_in[7];
    const float* w2   = (const float*)d_in[8];
    const float* bn2s = (const float*)d_in[9];
    const float* bn2b = (const float*)d_in[10];
    const float* bn2m = (const float*)d_in[11];
    const float* bn2v = (const float*)d_in[12];
    const float* vth2 = (const float*)d_in[13];
    const float* dec2 = (const float*)d_in[14];
    const float* w3   = (const float*)d_in[15];
    const float* bn3s = (const float*)d_in[16];
    const float* bn3b = (const float*)d_in[17];
    const float* bn3m = (const float*)d_in[18];
    const float* bn3v = (const float*)d_in[19];
    const float* dw   = (const float*)d_in[20];
    const float* db   = (const float*)d_in[21];
    const float* a1w  = (const float*)d_in[22];
    const float* a1b  = (const float*)d_in[23];
    const float* a2w  = (const float*)d_in[24];
    const float* a2b  = (const float*)d_in[25];

    float* out  = (float*)d_out;
    float* spk1 = out + 512;
    float* spk2 = spk1 + S1_;
    float* spk3 = spk2 + S2_;

    void *px1, *px2, *px3, *psp, *pw2, *pw3;
    cudaGetSymbolAddress(&px1, g_x1);
    cudaGetSymbolAddress(&px2, g_x2);
    cudaGetSymbolAddress(&px3, g_x3);
    cudaGetSymbolAddress(&psp, g_spkh);
    cudaGetSymbolAddress(&pw2, g_wt2);
    cudaGetSymbolAddress(&pw3, g_wt3);
    float* x1p = (float*)px1;
    float* x2p = (float*)px2;
    float* x3p = (float*)px3;
    __half* s1h = (__half*)psp;
    __half* s2h = s1h + SPK1_ELEMS;
    __half* wt2 = (__half*)pw2;
    __half* wt3 = (__half*)pw3;

    cudaFuncSetAttribute(conv_mma_kernel<C1, 4, 62, P1F, R1_, 32>,
                         cudaFuncAttributeMaxDynamicSharedMemorySize, CSMEM_BYTES);
    cudaFuncSetAttribute(conv_mma_kernel<C2, 12, 186, P2F, R2_, 64>,
                         cudaFuncAttributeMaxDynamicSharedMemorySize, CSMEM_BYTES);

    // Launch order (ncu -s 5 -c 1 => index 5 = conv2):
    // 0: wprep2 hi, 1: wprep2 lo, 2: wprep3, 3: conv1, 4: hlif1, 5: conv2
    wprep_kernel<0><<<(128*2048 + 255)/256, 256>>>(w2, wt2, 2048);
    wprep_kernel<1><<<(128*2048 + 255)/256, 256>>>(w2, wt2, 2048);
    wprep_both_kernel<<<(128*4096 + 255)/256, 256>>>(w3, wt3, 4096);

    conv1_bn_kernel<<<B_*T_/64, 256>>>(x, w1, bn1s, bn1b, bn1m, bn1v, x1p);
    hlif_kernel<C1, R1_, P1F, 16><<<B_*C1/128, 128>>>(x1p, spk1, s1h, vth1, dec1,
                                                      0.f, 1.f, 2.f, 1.f);
    conv_mma_kernel<C1, 4, 62, P1F, R1_, 32><<<PERSIST, 256, CSMEM_BYTES>>>(
        s1h, wt2, bn2s, bn2b, bn2m, bn2v, x2p);
    hlif_kernel<C2, R2_, P2F, 32><<<B_*C2/128, 128>>>(x2p, spk2, s2h, vth2, dec2,
                                                      0.f, 1.f, 2.f, 1.f);
    conv_mma_kernel<C2, 12, 186, P2F, R2_, 64><<<PERSIST, 256, CSMEM_BYTES>>>(
        s2h, wt3, bn3s, bn3b, bn3m, bn3v, x3p);
    alif_kernel<<<B_*C3/128, 128>>>(x3p, spk3);
    readout_kernel<<<B_, 256>>>(spk3, dw, db, a1w, a1b, a2w, a2b, out);
}

// round 17
// speedup vs baseline: 1.2997x; 1.0088x over previous
#include <cuda_runtime.h>
#include <cuda_fp16.h>
#include <cstdint>
#include <math.h>

#define B_  128
#define T_  480
#define C1  64
#define C2  128
#define C3  128

#define S1_ (B_*T_*C1)
#define S2_ (B_*T_*C2)
#define S3_ (B_*T_*C3)

#define P1F 64
#define R1_ (P1F + T_ + 160)      // 704 rows  (conv2 max row 637)
#define P2F 192
#define R2_ (P2F + T_ + 608)      // 1280 rows (conv3 max row 889)

#define SPK1_ELEMS ((long)B_*R1_*C1)
#define SPK2_ELEMS ((long)B_*R2_*C2)

#define LO_SCALE 2048.0f
#define LO_INV   (1.0f/2048.0f)

#define NTILES   1024
#define PERSIST  296             // 148 SM x 2 CTAs/SM

// ---------------- device scratch (allocation-free) ----------------
__device__ float g_x1[S1_];
__device__ float g_x2[S2_];
__device__ float g_x3[S3_];
__device__ __align__(256) __half g_spkh[SPK1_ELEMS + SPK2_ELEMS];
__device__ __align__(256) __half g_wt2[2*128*2048];   // [limb][o][kk]
__device__ __align__(256) __half g_wt3[2*128*4096];

// ---------------- PTX helpers ----------------
__device__ __forceinline__ uint32_t smem_to_u32(const void* p) {
    uint32_t a;
    asm("{ .reg .u64 t; cvta.to.shared.u64 t, %1; cvt.u32.u64 %0, t; }" : "=r"(a) : "l"(p));
    return a;
}
#define SWZ(x) ((x) ^ (((x) >> 3) & 0x70))

#define CP_ASYNC16(sa, gp) \
    asm volatile("cp.async.cg.shared.global [%0], [%1], 16;" \
        :: "r"(sa), "l"(__cvta_generic_to_global(gp)) : "memory")
#define CP_COMMIT() asm volatile("cp.async.commit_group;" ::: "memory")
#define CP_WAIT1()  asm volatile("cp.async.wait_group 1;" ::: "memory")
#define CP_WAIT0()  asm volatile("cp.async.wait_group 0;" ::: "memory")

#define LDSM_X4(r, addr) \
    asm volatile("ldmatrix.sync.aligned.m8n8.x4.shared.b16 {%0,%1,%2,%3}, [%4];" \
        : "=r"((r)[0]), "=r"((r)[1]), "=r"((r)[2]), "=r"((r)[3]) : "r"(addr))

#define MMA16816(c, a, b0, b1) \
    asm volatile("mma.sync.aligned.m16n8k16.row.col.f32.f16.f16.f32 " \
        "{%0,%1,%2,%3}, {%4,%5,%6,%7}, {%8,%9}, {%0,%1,%2,%3};" \
        : "+f"((c)[0]), "+f"((c)[1]), "+f"((c)[2]), "+f"((c)[3]) \
        : "r"((a)[0]), "r"((a)[1]), "r"((a)[2]), "r"((a)[3]), "r"(b0), "r"(b1))

// ---------------------------------------------------------------------------
// conv1 + BN1: register-tiled 64x64 GEMM per 64-row tile (R14 winner).
// ---------------------------------------------------------------------------
__global__ __launch_bounds__(256)
void conv1_bn_kernel(const float* __restrict__ x, const float* __restrict__ w1,
                     const float* __restrict__ sc, const float* __restrict__ bi,
                     const float* __restrict__ mn, const float* __restrict__ vr,
                     float* __restrict__ out) {
    const int LDP = 68;
    __shared__ float As[64*LDP];
    __shared__ float Bs[64*LDP];
    int tid = threadIdx.x;
    int tx = tid & 15, ty = tid >> 4;
    long row0 = (long)blockIdx.x*64;

    #pragma unroll
    for (int rep = 0; rep < 16; rep++) {
        int e = rep*256 + tid;
        int tl = e >> 6, w = e & 63;
        As[w*LDP + tl] = x[(row0 + tl)*64 + w];
        Bs[(e >> 6)*LDP + (e & 63)] = w1[e];
    }
    __syncthreads();

    float acc[4][4];
    #pragma unroll
    for (int r = 0; r < 4; r++)
        #pragma unroll
        for (int c = 0; c < 4; c++) acc[r][c] = 0.f;

    #pragma unroll 16
    for (int w = 0; w < 64; w++) {
        float4 a4 = *(const float4*)&As[w*LDP + ty*4];
        float4 b4 = *(const float4*)&Bs[w*LDP + tx*4];
        float ar[4] = {a4.x, a4.y, a4.z, a4.w};
        float br[4] = {b4.x, b4.y, b4.z, b4.w};
        #pragma unroll
        for (int r = 0; r < 4; r++)
            #pragma unroll
            for (int c = 0; c < 4; c++)
                acc[r][c] = fmaf(ar[r], br[c], acc[r][c]);
    }

    float gs[4], hb[4];
    #pragma unroll
    for (int c = 0; c < 4; c++) {
        int o = tx*4 + c;
        float inv = rsqrtf(vr[o] + 1e-5f);
        gs[c] = sc[o]*inv;
        hb[c] = bi[o] - mn[o]*gs[c];
    }
    #pragma unroll
    for (int r = 0; r < 4; r++) {
        long rw = (row0 + ty*4 + r)*64;
        float4 o4;
        o4.x = fmaf(acc[r][0], gs[0], hb[0]);
        o4.y = fmaf(acc[r][1], gs[1], hb[1]);
        o4.z = fmaf(acc[r][2], gs[2], hb[2]);
        o4.w = fmaf(acc[r][3], gs[3], hb[3]);
        *(float4*)&out[rw + tx*4] = o4;
    }
}

// ---------------------------------------------------------------------------
// Weight prep v2: smem-tiled transpose (coalesced read AND write) +
// 2-limb fp16 split (lo scaled by 2048).
// Grid: (KTOT/32, 128/32); block 32x8. Tile 32(kk) x 32(o).
// Read  w[kk][o]  (row-major, coalesced over o);
// write wt[o][kk] (row-major, coalesced over kk).
// ---------------------------------------------------------------------------
__global__ __launch_bounds__(256)
void wprep_kernel(const float* __restrict__ w, __half* __restrict__ wt, int KTOT) {
    __shared__ float tile[32][33];
    int kk0 = blockIdx.x*32, o0 = blockIdx.y*32;
    int tx = threadIdx.x, ty = threadIdx.y;
    #pragma unroll
    for (int r = 0; r < 4; r++) {
        int kk = kk0 + ty + r*8;
        tile[ty + r*8][tx] = w[(long)kk*128 + o0 + tx];
    }
    __syncthreads();
    #pragma unroll
    for (int r = 0; r < 4; r++) {
        int o = o0 + ty + r*8;
        float v = tile[tx][ty + r*8];
        __half hi = __float2half(v);
        long dst = (long)o*KTOT + kk0 + tx;
        wt[dst] = hi;
        wt[(long)128*KTOT + dst] = __float2half((v - __half2float(hi)) * LO_SCALE);
    }
}

// ---------------------------------------------------------------------------
// HLIF scan, DEPTH-deep software prefetch.
// ---------------------------------------------------------------------------
template<int C, int Rp, int PFp, int DEPTH>
__global__ __launch_bounds__(128)
void hlif_kernel(const float* __restrict__ xin, float* __restrict__ spk,
                 __half* __restrict__ spkh,
                 const float* __restrict__ vth_raw,
                 const float* __restrict__ decay_raw,
                 float v_m, float v_s, float d_m, float d_s) {
    int idx = blockIdx.x*128 + threadIdx.x;
    int b = idx / C, c = idx % C;
    float vth = log1pf(expf(vth_raw[c]*v_s + v_m)) + 0.5f;
    float decay = fminf(1.f/(1.f + expf(-(decay_raw[c]*d_s + d_m))), 0.99f);
    long base = (long)b*T_*C + c;
    long bb   = ((long)b*Rp + PFp)*C + c;
    float v = 0.f;
    float xv[DEPTH], xn[DEPTH];
    #pragma unroll
    for (int j = 0; j < DEPTH; j++) xv[j] = xin[base + (long)j*C];
    for (int t = 0; t < T_; t += DEPTH) {
        if (t + DEPTH < T_) {
            #pragma unroll
            for (int j = 0; j < DEPTH; j++) xn[j] = xin[base + (long)(t+DEPTH+j)*C];
        }
        #pragma unroll
        for (int j = 0; j < DEPTH; j++) {
            v = v*decay + xv[j];
            float s = (v - vth) > 0.f ? 1.f : 0.f;
            v -= s*vth;
            spk[base + (long)(t+j)*C] = s;
            spkh[bb + (long)(t+j)*C] = __float2half(s);
        }
        #pragma unroll
        for (int j = 0; j < DEPTH; j++) xv[j] = xn[j];
    }
}

// ---------------------------------------------------------------------------
// ALIF scan, 32-deep software prefetch.
// ---------------------------------------------------------------------------
__global__ __launch_bounds__(128)
void alif_kernel(const float* __restrict__ xin, float* __restrict__ spk) {
    const float d = 0.9f, adp = 0.9f, beta = 1.8f;
    int idx = blockIdx.x*128 + threadIdx.x;
    int b = idx / C3, c = idx % C3;
    long base = (long)b*T_*C3 + c;
    float v = 0.f, th = 0.f, ps = 0.f;
    float xv[32], xn[32];
    #pragma unroll
    for (int j = 0; j < 32; j++) xv[j] = xin[base + (long)j*C3];
    for (int t = 0; t < T_; t += 32) {
        if (t + 32 < T_) {
            #pragma unroll
            for (int j = 0; j < 32; j++) xn[j] = xin[base + (long)(t+32+j)*C3];
        }
        #pragma unroll
        for (int j = 0; j < 32; j++) {
            th = th*adp + ps*beta;
            v  = v*d + xv[j];
            float vt = 0.5f + th;
            float s = (v - vt) > 0.f ? 1.f : 0.f;
            v -= s*vt;
            ps = s;
            spk[base + (long)(t+j)*C3] = s;
        }
        #pragma unroll
        for (int j = 0; j < 32; j++) xv[j] = xn[j];
    }
}

// ---------------------------------------------------------------------------
// Persistent HMMA dilated conv + BN — static strided assignment (R16 winner).
// ---------------------------------------------------------------------------
#define STAGE_BYTES 32768
#define CSMEM_BYTES (3*STAGE_BYTES)

template<int CIN, int DIL, int PADL, int PF, int Rp, int NITER>
__global__ __launch_bounds__(256, 2)
void conv_mma_kernel(const __half* __restrict__ src, const __half* __restrict__ wt,
                     const float* __restrict__ sc, const float* __restrict__ bi,
                     const float* __restrict__ mn, const float* __restrict__ vr,
                     float* __restrict__ dst) {
    constexpr int KTOT = NITER*64;
    constexpr int CHUNKS = CIN/64;
    extern __shared__ char smem[];
    __shared__ float gsm[128], hbm[128];
    const int tid = threadIdx.x, lane = tid & 31, wid = tid >> 5;
    const int warpM = wid & 3, warpN = wid >> 2;   // 4(M) x 2(N)

    if (tid < 128) {
        float inv = rsqrtf(vr[tid] + 1e-5f);
        float g = sc[tid]*inv;
        gsm[tid] = g;
        hbm[tid] = bi[tid] - mn[tid]*g;
    }
    __syncthreads();

    const uint32_t sbase = smem_to_u32(smem);

    for (int tile = blockIdx.x; tile < NTILES; tile += PERSIST) {
        const int b     = tile >> 3;
        const int mtile = (tile >> 1) & 3;
        const int oBase = (tile & 1)*64;
        const __half* sb = src + (long)b*Rp*CIN;

        float accH[2][4][4] = {};
        float accL[2][4][4] = {};

        auto issue = [&](int it) {
            const uint32_t stage = sbase + (uint32_t)(it % 3)*(uint32_t)STAGE_BYTES;
            const int k  = it / CHUNKS;
            const int c0 = (it % CHUNKS)*64;
            const long arow0 = (long)(PF + mtile*128 + k*DIL - PADL);
            #pragma unroll
            for (int rep = 0; rep < 4; rep++) {
                int idx = rep*256 + tid;
                int row = idx >> 3, seg = idx & 7;
                const __half* gp = sb + (arow0 + row)*CIN + c0 + seg*8;
                CP_ASYNC16(stage + SWZ(row*128 + seg*16), gp);
            }
            #pragma unroll
            for (int limb = 0; limb < 2; limb++) {
                const __half* wp = wt + (long)limb*128*KTOT + (long)oBase*KTOT + it*64;
                #pragma unroll
                for (int rep = 0; rep < 2; rep++) {
                    int idx = rep*256 + tid;
                    int row = idx >> 3, seg = idx & 7;
                    const __half* gp = wp + (long)row*KTOT + seg*8;
                    CP_ASYNC16(stage + 16384u + (uint32_t)limb*8192u + SWZ(row*128 + seg*16), gp);
                }
            }
            CP_COMMIT();
        };

        issue(0);
        issue(1);
        __syncthreads();

        for (int it = 0; it < NITER; it++) {
            if (it + 2 < NITER) CP_WAIT1(); else CP_WAIT0();
            __syncthreads();
            if (it + 2 < NITER) issue(it + 2);

            const uint32_t stage = sbase + (uint32_t)(it % 3)*(uint32_t)STAGE_BYTES;

            #pragma unroll
            for (int ks = 0; ks < 4; ks++) {
                uint32_t a[2][4];
                #pragma unroll
                for (int mf = 0; mf < 2; mf++) {
                    int row = warpM*32 + mf*16 + (lane & 15);
                    LDSM_X4(a[mf], stage + SWZ(row*128 + ks*32 + (lane >> 4)*16));
                }
                #pragma unroll
                for (int limb = 0; limb < 2; limb++) {
                    const uint32_t bbp = stage + 16384u + (uint32_t)limb*8192u;
                    #pragma unroll
                    for (int np = 0; np < 2; np++) {
                        int row = warpN*32 + np*16 + ((lane >> 4) << 3) + (lane & 7);
                        uint32_t q[4];
                        LDSM_X4(q, bbp + SWZ(row*128 + ks*32 + ((lane >> 3) & 1)*16));
                        if (limb == 0) {
                            #pragma unroll
                            for (int mf = 0; mf < 2; mf++) {
                                MMA16816(accH[mf][np*2],     a[mf], q[0], q[1]);
                                MMA16816(accH[mf][np*2 + 1], a[mf], q[2], q[3]);
                            }
                        } else {
                            #pragma unroll
                            for (int mf = 0; mf < 2; mf++) {
                                MMA16816(accL[mf][np*2],     a[mf], q[0], q[1]);
                                MMA16816(accL[mf][np*2 + 1], a[mf], q[2], q[3]);
                            }
                        }
                    }
                }
            }
        }

        #pragma unroll
        for (int mf = 0; mf < 2; mf++) {
            #pragma unroll
            for (int h = 0; h < 2; h++) {
                int t = mtile*128 + warpM*32 + mf*16 + (lane >> 2) + h*8;
                if (t < T_) {
                    long dr = ((long)b*T_ + t)*128 + oBase;
                    #pragma unroll
                    for (int ng = 0; ng < 4; ng++) {
                        int lc = warpN*32 + ng*8 + (lane & 3)*2;
                        float v0 = fmaf(accL[mf][ng][h*2],     LO_INV, accH[mf][ng][h*2]);
                        float v1 = fmaf(accL[mf][ng][h*2 + 1], LO_INV, accH[mf][ng][h*2 + 1]);
                        float2 o;
                        o.x = fmaf(v0, gsm[oBase + lc],   hbm[oBase + lc]);
                        o.y = fmaf(v1, gsm[oBase + lc+1], hbm[oBase + lc+1]);
                        *(float2*)&dst[dr + lc] = o;
                    }
                }
            }
        }
        __syncthreads();
    }
}

// ---------------------------------------------------------------------------
// Readout: dense -> LI scan -> window diff -> attention -> logits
// ---------------------------------------------------------------------------
__global__ __launch_bounds__(256)
void readout_kernel(const float* __restrict__ spk3,
                    const float* __restrict__ dw, const float* __restrict__ db,
                    const float* __restrict__ a1w, const float* __restrict__ a1b,
                    const float* __restrict__ a2w, const float* __restrict__ a2b,
                    float* __restrict__ logits) {
    __shared__ float vseq[T_*4];
    __shared__ float dp[20*4];
    __shared__ float hsm[20*8];
    __shared__ float score[20];
    __shared__ float wsm[128*4];
    int b = blockIdx.x, tid = threadIdx.x;
    for (int e = tid; e < 512; e += 256) wsm[e] = dw[e];
    __syncthreads();
    const float* sp = spk3 + (long)b*T_*C3;
    for (int e = tid; e < T_*4; e += 256) {
        int t = e >> 2, j = e & 3;
        float accv = db[j];
        const float* row = sp + (long)t*C3;
        #pragma unroll 8
        for (int c = 0; c < 128; c++) accv = fmaf(row[c], wsm[c*4 + j], accv);
        vseq[e] = accv;
    }
    __syncthreads();
    if (tid < 4) {
        float v = 0.f;
        const float dec = 0.9f, odec = 0.1f;
        for (int t = 0; t < T_; t++) {
            v = fmaf(v, dec, vseq[t*4 + tid]*odec);
            vseq[t*4 + tid] = v;
        }
    }
    __syncthreads();
    if (tid < 80) {
        int g = tid >> 2, j = tid & 3;
        float s1 = 0.f, s2 = 0.f;
        #pragma unroll
        for (int u = 0; u < 12; u++) {
            s1 += vseq[(g*24 + u)*4 + j];
            s2 += vseq[(g*24 + 12 + u)*4 + j];
        }
        dp[g*4 + j] = (s2 - s1)*(1.f/12.f);
    }
    __syncthreads();
    if (tid < 160) {
        int g = tid >> 3, u = tid & 7;
        float a = a1b[u];
        #pragma unroll
        for (int j = 0; j < 4; j++) a = fmaf(dp[g*4 + j], a1w[j*8 + u], a);
        hsm[g*8 + u] = fmaxf(a, 0.f);
    }
    __syncthreads();
    if (tid < 20) {
        float a = a2b[0];
        #pragma unroll
        for (int u = 0; u < 8; u++) a = fmaf(hsm[tid*8 + u], a2w[u], a);
        score[tid] = a;
    }
    __syncthreads();
    if (tid < 4) {
        float m = -1e30f;
        #pragma unroll
        for (int g = 0; g < 20; g++) m = fmaxf(m, score[g]);
        float den = 0.f, accv = 0.f;
        #pragma unroll
        for (int g = 0; g < 20; g++) {
            float e = expf(score[g] - m);
            den += e;
            accv = fmaf(dp[g*4 + tid], e, accv);
        }
        logits[b*4 + tid] = accv/den;
    }
}

// ---------------------------------------------------------------------------
extern "C" void kernel_launch(void* const* d_in, const int* in_sizes, int n_in,
                              void* d_out, int out_size) {
    const float* x    = (const float*)d_in[0];
    const float* w1   = (const float*)d_in[1];
    const float* bn1s = (const float*)d_in[2];
    const float* bn1b = (const float*)d_in[3];
    const float* bn1m = (const float*)d_in[4];
    const float* bn1v = (const float*)d_in[5];
    const float* vth1 = (const float*)d_in[6];
    const float* dec1 = (const float*)d_in[7];
    const float* w2   = (const float*)d_in[8];
    const float* bn2s = (const float*)d_in[9];
    const float* bn2b = (const float*)d_in[10];
    const float* bn2m = (const float*)d_in[11];
    const float* bn2v = (const float*)d_in[12];
    const float* vth2 = (const float*)d_in[13];
    const float* dec2 = (const float*)d_in[14];
    const float* w3   = (const float*)d_in[15];
    const float* bn3s = (const float*)d_in[16];
    const float* bn3b = (const float*)d_in[17];
    const float* bn3m = (const float*)d_in[18];
    const float* bn3v = (const float*)d_in[19];
    const float* dw   = (const float*)d_in[20];
    const float* db   = (const float*)d_in[21];
    const float* a1w  = (const float*)d_in[22];
    const float* a1b  = (const float*)d_in[23];
    const float* a2w  = (const float*)d_in[24];
    const float* a2b  = (const float*)d_in[25];

    float* out  = (float*)d_out;
    float* spk1 = out + 512;
    float* spk2 = spk1 + S1_;
    float* spk3 = spk2 + S2_;

    void *px1, *px2, *px3, *psp, *pw2, *pw3;
    cudaGetSymbolAddress(&px1, g_x1);
    cudaGetSymbolAddress(&px2, g_x2);
    cudaGetSymbolAddress(&px3, g_x3);
    cudaGetSymbolAddress(&psp, g_spkh);
    cudaGetSymbolAddress(&pw2, g_wt2);
    cudaGetSymbolAddress(&pw3, g_wt3);
    float* x1p = (float*)px1;
    float* x2p = (float*)px2;
    float* x3p = (float*)px3;
    __half* s1h = (__half*)psp;
    __half* s2h = s1h + SPK1_ELEMS;
    __half* wt2 = (__half*)pw2;
    __half* wt3 = (__half*)pw3;

    cudaFuncSetAttribute(conv_mma_kernel<C1, 4, 62, P1F, R1_, 32>,
                         cudaFuncAttributeMaxDynamicSharedMemorySize, CSMEM_BYTES);
    cudaFuncSetAttribute(conv_mma_kernel<C2, 12, 186, P2F, R2_, 64>,
                         cudaFuncAttributeMaxDynamicSharedMemorySize, CSMEM_BYTES);

    // Launch order: wprep2(0), conv1(1), hlif1(2), conv2(3) <- profiled slot,
    // wprep3(4), hlif2(5), conv3(6), alif(7), readout(8).
    // wt3 is ready before conv3; all dependencies preserved on one stream.
    wprep_kernel<<<dim3(2048/32, 128/32), dim3(32, 8)>>>(w2, wt2, 2048);
    conv1_bn_kernel<<<B_*T_/64, 256>>>(x, w1, bn1s, bn1b, bn1m, bn1v, x1p);
    hlif_kernel<C1, R1_, P1F, 16><<<B_*C1/128, 128>>>(x1p, spk1, s1h, vth1, dec1,
                                                      0.f, 1.f, 2.f, 1.f);
    conv_mma_kernel<C1, 4, 62, P1F, R1_, 32><<<PERSIST, 256, CSMEM_BYTES>>>(
        s1h, wt2, bn2s, bn2b, bn2m, bn2v, x2p);
    wprep_kernel<<<dim3(4096/32, 128/32), dim3(32, 8)>>>(w3, wt3, 4096);
    hlif_kernel<C2, R2_, P2F, 32><<<B_*C2/128, 128>>>(x2p, spk2, s2h, vth2, dec2,
                                                      0.f, 1.f, 2.f, 1.f);
    conv_mma_kernel<C2, 12, 186, P2F, R2_, 64><<<PERSIST, 256, CSMEM_BYTES>>>(
        s2h, wt3, bn3s, bn3b, bn3m, bn3v, x3p);
    alif_kernel<<<B_*C3/128, 128>>>(x3p, spk3);
    readout_kernel<<<B_, 256>>>(spk3, dw, db, a1w, a1b, a2w, a2b, out);
}